// round 1
// baseline (speedup 1.0000x reference)
#include <cuda_runtime.h>

#define D_VOCAB 50257
#define D_MODEL 768
#define N_ROWS  4096          // BATCH * POS = 2 * 2048
#define SQRT_DM 27.712812921102035f   // sqrt(768)

// Scratch for the per-row argmax indices (device global — no allocations allowed).
__device__ int g_indices[N_ROWS];

// Phase 1: streaming scan of the one-hot tensor (flat, float4-vectorized).
// Exactly one nonzero per row, so plain stores to g_indices are race-free.
__global__ void __launch_bounds__(256) find_indices_kernel(
    const float4* __restrict__ tokens4, long n4)
{
    long i = (long)blockIdx.x * blockDim.x + threadIdx.x;
    const long stride = (long)gridDim.x * blockDim.x;
    #pragma unroll 4
    for (; i < n4; i += stride) {
        float4 v = tokens4[i];
        if (v.x != 0.0f || v.y != 0.0f || v.z != 0.0f || v.w != 0.0f) {
            long base = i * 4;
            float vals[4] = {v.x, v.y, v.z, v.w};
            #pragma unroll
            for (int j = 0; j < 4; j++) {
                if (vals[j] != 0.0f) {
                    long flat = base + j;
                    int row = (int)(flat / D_VOCAB);
                    int col = (int)(flat - (long)row * D_VOCAB);
                    g_indices[row] = col;
                }
            }
        }
    }
}

// Phase 2: gather embedding rows, scale by sqrt(d_model), add bias.
// One block per (batch, pos) row; 192 threads x float4 = 768 floats.
__global__ void __launch_bounds__(192) gather_kernel(
    const float* __restrict__ W,
    const float* __restrict__ bias,
    float* __restrict__ out)
{
    int row = blockIdx.x;
    int t   = threadIdx.x;  // 0..191
    int idx = g_indices[row];

    const float4* wrow = reinterpret_cast<const float4*>(W + (long)idx * D_MODEL);
    const float4* b4   = reinterpret_cast<const float4*>(bias);

    float4 w = wrow[t];
    float4 b = b4[t];
    float4 o;
    o.x = fmaf(w.x, SQRT_DM, b.x);
    o.y = fmaf(w.y, SQRT_DM, b.y);
    o.z = fmaf(w.z, SQRT_DM, b.z);
    o.w = fmaf(w.w, SQRT_DM, b.w);

    reinterpret_cast<float4*>(out)[(long)row * (D_MODEL / 4) + t] = o;
}

extern "C" void kernel_launch(void* const* d_in, const int* in_sizes, int n_in,
                              void* d_out, int out_size)
{
    const float* tokens = (const float*)d_in[0];   // [2, 2048, 50257] one-hot fp32
    const float* W      = (const float*)d_in[1];   // [50257, 768]
    const float* bias   = (const float*)d_in[2];   // [768]
    float* out          = (float*)d_out;           // [2, 2048, 768]

    const long n_elems = (long)N_ROWS * D_VOCAB;   // 205,852,672 (divisible by 4)
    const long n4 = n_elems / 4;

    find_indices_kernel<<<4096, 256>>>(reinterpret_cast<const float4*>(tokens), n4);
    gather_kernel<<<N_ROWS, 192>>>(W, bias, out);
}

// round 2
// speedup vs baseline: 1.1870x; 1.1870x over previous
#include <cuda_runtime.h>
#include <cstdint>

#define D_VOCAB 50257
#define D_MODEL 768
#define N_ROWS  4096          // BATCH * POS = 2 * 2048
#define SQRT_DM 27.712812921102035f   // sqrt(768)
#define NTHREADS 256

// One block per (batch,pos) row: scan that row's 50257 one-hot floats for the
// single nonzero, then gather the embedding row, scale, add bias, store.
// one_hot values are exactly 0.0f / 1.0f, so integer-nonzero checks are exact.
__global__ void __launch_bounds__(NTHREADS) embed_fused_kernel(
    const float* __restrict__ tokens,
    const float* __restrict__ W,
    const float* __restrict__ bias,
    float* __restrict__ out)
{
    const int row = blockIdx.x;
    const int tid = threadIdx.x;
    const float* rp = tokens + (long)row * D_VOCAB;

    __shared__ int s_col;   // written by exactly one thread (one nonzero/row)

    // ---- alignment: row start is (row mod 4) floats past a 16B boundary ----
    const int mis = (int)(((uintptr_t)rp >> 2) & 3);   // elements past 16B align
    const int pre = (4 - mis) & 3;                     // scalar prologue count

    if (tid < pre) {
        if (__float_as_uint(rp[tid]) != 0u) s_col = tid;
    }

    const uint4* __restrict__ p4 = reinterpret_cast<const uint4*>(rp + pre);
    const int n4   = (D_VOCAB - pre) >> 2;
    const int tail = (D_VOCAB - pre) & 3;

    // ---- streaming scan body: LDG.128, integer nonzero check ----
    #pragma unroll 4
    for (int i = tid; i < n4; i += NTHREADS) {
        uint4 v = p4[i];
        if (v.x | v.y | v.z | v.w) {
            int base = pre + (i << 2);
            if (v.x) s_col = base;
            if (v.y) s_col = base + 1;
            if (v.z) s_col = base + 2;
            if (v.w) s_col = base + 3;
        }
    }

    // ---- scalar tail ----
    const int tstart = pre + (n4 << 2);
    if (tid < tail) {
        if (__float_as_uint(rp[tstart + tid]) != 0u) s_col = tstart + tid;
    }

    __syncthreads();
    const int col = s_col;

    // ---- gather + scale + bias: 192 threads x float4 = 768 floats ----
    if (tid < D_MODEL / 4) {
        const float4 w = reinterpret_cast<const float4*>(W + (long)col * D_MODEL)[tid];
        const float4 b = reinterpret_cast<const float4*>(bias)[tid];
        float4 o;
        o.x = fmaf(w.x, SQRT_DM, b.x);
        o.y = fmaf(w.y, SQRT_DM, b.y);
        o.z = fmaf(w.z, SQRT_DM, b.z);
        o.w = fmaf(w.w, SQRT_DM, b.w);
        reinterpret_cast<float4*>(out)[(long)row * (D_MODEL / 4) + tid] = o;
    }
}

extern "C" void kernel_launch(void* const* d_in, const int* in_sizes, int n_in,
                              void* d_out, int out_size)
{
    const float* tokens = (const float*)d_in[0];   // [2, 2048, 50257] one-hot fp32
    const float* W      = (const float*)d_in[1];   // [50257, 768]
    const float* bias   = (const float*)d_in[2];   // [768]
    float* out          = (float*)d_out;           // [2, 2048, 768]

    embed_fused_kernel<<<N_ROWS, NTHREADS>>>(tokens, W, bias, out);
}

// round 3
// speedup vs baseline: 1.2775x; 1.0762x over previous
#include <cuda_runtime.h>
#include <cstdint>

#define D_VOCAB 50257
#define D_MODEL 768
#define N_ROWS  4096          // BATCH * POS = 2 * 2048
#define SQRT_DM 27.712812921102035f   // sqrt(768)
#define NTHREADS 256

// Two blocks per (batch,pos) row; each scans half of that row's 50257 one-hot
// floats. The block whose half contains the single nonzero performs the
// gather+scale+bias for the row. one_hot values are exactly 0.0f/1.0f, so
// integer-nonzero checks are exact.
__global__ void __launch_bounds__(NTHREADS) embed_fused_kernel(
    const float* __restrict__ tokens,
    const float* __restrict__ W,
    const float* __restrict__ bias,
    float* __restrict__ out)
{
    const int row  = blockIdx.x >> 1;
    const int half = blockIdx.x & 1;
    const int tid  = threadIdx.x;
    const float* rp = tokens + (long)row * D_VOCAB;

    __shared__ int s_col;
    if (tid == 0) s_col = -1;
    __syncthreads();

    // Row start is (row*50257 mod 4) floats past a 16B boundary.
    const int mis = (int)(((uintptr_t)rp >> 2) & 3);
    const int pre = (4 - mis) & 3;                 // scalar prologue count

    const uint4* __restrict__ p4 = reinterpret_cast<const uint4*>(rp + pre);
    const int n4   = (D_VOCAB - pre) >> 2;
    const int tail = (D_VOCAB - pre) & 3;
    const int n4h  = n4 >> 1;                      // half0: [0,n4h)  half1: [n4h,n4)

    if (half == 0) {
        if (tid < pre && __float_as_uint(rp[tid]) != 0u) s_col = tid;

        #pragma unroll 8
        for (int i = tid; i < n4h; i += NTHREADS) {
            uint4 v = __ldcs(p4 + i);              // streaming: evict-first
            if (v.x | v.y | v.z | v.w) {
                int base = pre + (i << 2);
                if (v.x) s_col = base;
                if (v.y) s_col = base + 1;
                if (v.z) s_col = base + 2;
                if (v.w) s_col = base + 3;
            }
        }
    } else {
        #pragma unroll 8
        for (int i = n4h + tid; i < n4; i += NTHREADS) {
            uint4 v = __ldcs(p4 + i);
            if (v.x | v.y | v.z | v.w) {
                int base = pre + (i << 2);
                if (v.x) s_col = base;
                if (v.y) s_col = base + 1;
                if (v.z) s_col = base + 2;
                if (v.w) s_col = base + 3;
            }
        }
        const int tstart = pre + (n4 << 2);
        if (tid < tail && __float_as_uint(rp[tstart + tid]) != 0u)
            s_col = tstart + tid;
    }

    __syncthreads();
    const int col = s_col;

    // Only the half that found the nonzero emits the output row.
    if (col >= 0 && tid < D_MODEL / 4) {
        const float4 w = reinterpret_cast<const float4*>(W + (long)col * D_MODEL)[tid];
        const float4 b = reinterpret_cast<const float4*>(bias)[tid];
        float4 o;
        o.x = fmaf(w.x, SQRT_DM, b.x);
        o.y = fmaf(w.y, SQRT_DM, b.y);
        o.z = fmaf(w.z, SQRT_DM, b.z);
        o.w = fmaf(w.w, SQRT_DM, b.w);
        reinterpret_cast<float4*>(out)[(long)row * (D_MODEL / 4) + tid] = o;
    }
}

extern "C" void kernel_launch(void* const* d_in, const int* in_sizes, int n_in,
                              void* d_out, int out_size)
{
    const float* tokens = (const float*)d_in[0];   // [2, 2048, 50257] one-hot fp32
    const float* W      = (const float*)d_in[1];   // [50257, 768]
    const float* bias   = (const float*)d_in[2];   // [768]
    float* out          = (float*)d_out;           // [2, 2048, 768]

    embed_fused_kernel<<<2 * N_ROWS, NTHREADS>>>(tokens, W, bias, out);
}